// round 4
// baseline (speedup 1.0000x reference)
#include <cuda_runtime.h>
#include <cuda_bf16.h>

#define T_SEQ 34
#define NTOK  14
#define NE    476   // 34*14 distinct (position, token) variants

typedef unsigned long long u64;
typedef unsigned int       u32;

// LUTs built by prologue kernel (device globals: no allocation allowed)
__device__ float2 g_q[NE * 3];   // prescaled q, packed (head0, head1) per dim
__device__ u64    g_kv[NE * 3];  // bf16x4 per u64: {k_d pairs, v_d pairs}
__device__ float2 g_x[NE * 3];   // raw embedded x (pre-LN), for residual

// ---------- packed f32x2 helpers (sm_103a) ----------
__device__ __forceinline__ u64 pk2(float a, float b) {
    u64 r; asm("mov.b64 %0,{%1,%2};" : "=l"(r) : "f"(a), "f"(b)); return r;
}
__device__ __forceinline__ u64 pk2f(float2 f) { return pk2(f.x, f.y); }
__device__ __forceinline__ float2 upk2(u64 v) {
    float2 f; asm("mov.b64 {%0,%1},%2;" : "=f"(f.x), "=f"(f.y) : "l"(v)); return f;
}
__device__ __forceinline__ u64 rep2(float a) {
    u64 r; asm("mov.b64 %0,{%1,%1};" : "=l"(r) : "f"(a)); return r;
}
__device__ __forceinline__ u64 fma2(u64 a, u64 b, u64 c) {
    u64 d; asm("fma.rn.f32x2 %0,%1,%2,%3;" : "=l"(d) : "l"(a), "l"(b), "l"(c)); return d;
}
__device__ __forceinline__ u64 add2(u64 a, u64 b) {
    u64 d; asm("add.rn.f32x2 %0,%1,%2;" : "=l"(d) : "l"(a), "l"(b)); return d;
}
__device__ __forceinline__ u64 mul2(u64 a, u64 b) {
    u64 d; asm("mul.rn.f32x2 %0,%1,%2;" : "=l"(d) : "l"(a), "l"(b)); return d;
}
// bf16x2 (lo=head0, hi=head1) -> f32x2
__device__ __forceinline__ u64 bfpair(u32 u) {
    u32 lo = u << 16, hi = u & 0xffff0000u;
    u64 r; asm("mov.b64 %0,{%1,%2};" : "=l"(r) : "r"(lo), "r"(hi)); return r;
}
__device__ __forceinline__ float fex2(float x) { float r; asm("ex2.approx.f32 %0,%1;" : "=f"(r) : "f"(x)); return r; }
__device__ __forceinline__ float frcp(float x) { float r; asm("rcp.approx.f32 %0,%1;" : "=f"(r) : "f"(x)); return r; }
__device__ __forceinline__ float frsq(float x) { float r; asm("rsqrt.approx.f32 %0,%1;" : "=f"(r) : "f"(x)); return r; }

__device__ __forceinline__ unsigned short bfb(float f) {
    return __bfloat16_as_ushort(__float2bfloat16_rn(f));
}

// ---------- prologue: build 476-entry LUTs ----------
__global__ void build_luts(const float* __restrict__ tok_emb, const float* __restrict__ pos_enc,
                           const float* __restrict__ wq, const float* __restrict__ wk,
                           const float* __restrict__ wv,
                           const float* __restrict__ g1, const float* __restrict__ b1) {
    int e = blockIdx.x * blockDim.x + threadIdx.x;
    if (e >= NE) return;
    int t = e / NTOK, c = e % NTOK;
    float x[6];
    x[0] = tok_emb[c * 3 + 0]; x[1] = tok_emb[c * 3 + 1]; x[2] = tok_emb[c * 3 + 2];
    x[3] = pos_enc[t * 3 + 0]; x[4] = pos_enc[t * 3 + 1]; x[5] = pos_enc[t * 3 + 2];
    float s = 0.f;
#pragma unroll
    for (int i = 0; i < 6; i++) s += x[i];
    float mu = s * (1.f / 6.f);
    float v = 0.f;
#pragma unroll
    for (int i = 0; i < 6; i++) { float d = x[i] - mu; v += d * d; }
    v *= (1.f / 6.f);
    float r = frsq(v + 1e-5f);
    float n[6];
#pragma unroll
    for (int i = 0; i < 6; i++) n[i] = (x[i] - mu) * r * g1[i] + b1[i];

    float q[6], k[6], vv[6];  // index = h*3+d
#pragma unroll
    for (int j = 0; j < 6; j++) {
        q[j]  = n[3] * wq[j] + n[4] * wq[6 + j] + n[5] * wq[12 + j];
        k[j]  = n[3] * wk[j] + n[4] * wk[6 + j] + n[5] * wk[12 + j];
        vv[j] = n[0] * wv[j] + n[1] * wv[6 + j] + n[2] * wv[12 + j];
    }
    // fold 1/sqrt(HEAD_DIM) and log2(e) into q (inner loop uses ex2)
    const float qs = 1.4426950408889634f * 0.57735026918962576f;
    float2* qp = g_q + e * 3;
#pragma unroll
    for (int d = 0; d < 3; d++) qp[d] = make_float2(q[d] * qs, q[3 + d] * qs);

    u32 w[6];
#pragma unroll
    for (int d = 0; d < 3; d++) {
        w[d]     = ((u32)bfb(k[3 + d])  << 16) | (u32)bfb(k[d]);
        w[3 + d] = ((u32)bfb(vv[3 + d]) << 16) | (u32)bfb(vv[d]);
    }
    u64* kvp = g_kv + e * 3;
    kvp[0] = ((u64)w[1] << 32) | w[0];
    kvp[1] = ((u64)w[3] << 32) | w[2];
    kvp[2] = ((u64)w[5] << 32) | w[4];

    float2* xp = g_x + e * 3;
    xp[0] = make_float2(x[0], x[1]);
    xp[1] = make_float2(x[2], x[3]);
    xp[2] = make_float2(x[4], x[5]);
}

// ---------- per-token layernorm over 6 dims ----------
__device__ __forceinline__ void ln6(const float* x, float* o, const float* g, const float* b) {
    float s = 0.f;
#pragma unroll
    for (int i = 0; i < 6; i++) s += x[i];
    float mu = s * (1.f / 6.f);
    float v = 0.f;
#pragma unroll
    for (int i = 0; i < 6; i++) { float d = x[i] - mu; v += d * d; }
    v *= (1.f / 6.f);
    float r = frsq(v + 1e-5f);
#pragma unroll
    for (int i = 0; i < 6; i++) o[i] = (x[i] - mu) * r * g[i] + b[i];
}

__device__ __forceinline__ float gelu_exact(float x) {
    return 0.5f * x * (1.f + erff(x * 0.70710678118654752f));
}

// ---------- main kernel: 32 sequences/block, 17 warps, warp y does tokens {y, 33-y} ----------
__global__ void __launch_bounds__(544, 1)
tf_main(const int* __restrict__ idx, float* __restrict__ out,
        const float* __restrict__ wo, const float* __restrict__ g2, const float* __restrict__ bb2,
        const float* __restrict__ w1, const float* __restrict__ b1v,
        const float* __restrict__ w2, const float* __restrict__ b2v,
        const float* __restrict__ gf, const float* __restrict__ bfv,
        const float* __restrict__ wh) {
    __shared__ float2 sh_q[NE * 3];
    __shared__ u64    sh_kv[NE * 3];
    __shared__ float2 sh_x[NE * 3];
    __shared__ int    sh_off[T_SEQ * 32];
    __shared__ __align__(16) float sw[288];

    const int NT = 544;
    int tid = threadIdx.y * 32 + threadIdx.x;
    int base = blockIdx.x * 32;

    for (int i = tid; i < NE * 3; i += NT) {
        sh_q[i]  = g_q[i];
        sh_kv[i] = g_kv[i];
        sh_x[i]  = g_x[i];
    }
    for (int i = tid; i < 288; i += NT) sw[i] = 0.f;
    for (int i = tid; i < T_SEQ * 32; i += NT) {
        int k = i >> 5, ln = i & 31;
        sh_off[i] = (k * NTOK + idx[(base + ln) * T_SEQ + k]) * 3;  // u64-index into sh_kv
    }
    __syncthreads();
    // structured weight fill (padding already zeroed)
    if (tid < 36)       { sw[(tid / 6) * 8 + tid % 6] = wo[tid]; }
    else if (tid < 72)  { int i = tid - 36;  sw[48  + (i / 6) * 8  + i % 6]  = w1[i]; }
    else if (tid < 108) { int i = tid - 72;  sw[96  + (i / 6) * 8  + i % 6]  = w2[i]; }
    else if (tid < 192) { int i = tid - 108; sw[144 + (i / 14) * 16 + i % 14] = wh[i]; }
    else if (tid < 198) { sw[240 + tid - 192] = b1v[tid - 192]; }
    else if (tid < 204) { sw[248 + tid - 198] = b2v[tid - 198]; }
    else if (tid < 210) { sw[256 + tid - 204] = g2[tid - 204]; }
    else if (tid < 216) { sw[264 + tid - 210] = bb2[tid - 210]; }
    else if (tid < 222) { sw[272 + tid - 216] = gf[tid - 216]; }
    else if (tid < 228) { sw[280 + tid - 222] = bfv[tid - 222]; }
    __syncthreads();

    int lane = threadIdx.x, y = threadIdx.y;
    int t1 = y, t2 = 33 - y;                     // warp-uniform
    int e1 = sh_off[t1 * 32 + lane] / 3;         // LUT entry for own token
    int e2 = sh_off[t2 * 32 + lane] / 3;

    u64 q1[3], q2v[3];
    {
        const float2* p = sh_q + e1 * 3;
        q1[0] = pk2f(p[0]); q1[1] = pk2f(p[1]); q1[2] = pk2f(p[2]);
        const float2* r = sh_q + e2 * 3;
        q2v[0] = pk2f(r[0]); q2v[1] = pk2f(r[1]); q2v[2] = pk2f(r[2]);
    }

    u64 acc1[3] = {0, 0, 0}, acc2[3] = {0, 0, 0};
    u64 den1 = 0, den2 = 0;   // packed (0.f,0.f)

#pragma unroll 2
    for (int k = 0; k <= t2; k++) {
        int o3 = sh_off[k * 32 + lane];
        u64 kv0 = sh_kv[o3], kv1 = sh_kv[o3 + 1], kv2 = sh_kv[o3 + 2];
        u64 K0 = bfpair((u32)kv0), K1 = bfpair((u32)(kv0 >> 32)), K2 = bfpair((u32)kv1);
        u64 V0 = bfpair((u32)(kv1 >> 32)), V1 = bfpair((u32)kv2), V2 = bfpair((u32)(kv2 >> 32));

        u64 s2 = fma2(q2v[0], K0, fma2(q2v[1], K1, mul2(q2v[2], K2)));
        float2 sf = upk2(s2);
        u64 w2p = pk2(fex2(sf.x), fex2(sf.y));
        den2 = add2(den2, w2p);
        acc2[0] = fma2(w2p, V0, acc2[0]);
        acc2[1] = fma2(w2p, V1, acc2[1]);
        acc2[2] = fma2(w2p, V2, acc2[2]);

        if (k <= t1) {   // prefix of the same loop: shared K/V reads
            u64 s1 = fma2(q1[0], K0, fma2(q1[1], K1, mul2(q1[2], K2)));
            float2 s1f = upk2(s1);
            u64 w1p = pk2(fex2(s1f.x), fex2(s1f.y));
            den1 = add2(den1, w1p);
            acc1[0] = fma2(w1p, V0, acc1[0]);
            acc1[1] = fma2(w1p, V1, acc1[1]);
            acc1[2] = fma2(w1p, V2, acc1[2]);
        }
    }

    float o1[6], o2[6];   // [h*3+d]
    {
        float2 d1 = upk2(den1); float r0 = frcp(d1.x), r1 = frcp(d1.y);
#pragma unroll
        for (int d = 0; d < 3; d++) { float2 a = upk2(acc1[d]); o1[d] = a.x * r0; o1[3 + d] = a.y * r1; }
        float2 d2 = upk2(den2); float s0 = frcp(d2.x), s1 = frcp(d2.y);
#pragma unroll
        for (int d = 0; d < 3; d++) { float2 a = upk2(acc2[d]); o2[d] = a.x * s0; o2[3 + d] = a.y * s1; }
    }

    // ---------- epilogue, both tokens interleaved (weight rows loaded once) ----------
    const u64* woP = (const u64*)sw;            // rows j: woP[j*4 + p], p<3
    const u64* w1P = (const u64*)(sw + 48);
    const u64* w2P = (const u64*)(sw + 96);
    const u64* whP = (const u64*)(sw + 144);    // rows i: whP[i*8 + p], p<7
    const u64* b1P = (const u64*)(sw + 240);
    const u64* b2P = (const u64*)(sw + 248);

    u64 x1a[3], x1b[3];
    {
        const float2* p = sh_x + e1 * 3;
        x1a[0] = pk2f(p[0]); x1a[1] = pk2f(p[1]); x1a[2] = pk2f(p[2]);
        const float2* r = sh_x + e2 * 3;
        x1b[0] = pk2f(r[0]); x1b[1] = pk2f(r[1]); x1b[2] = pk2f(r[2]);
    }
#pragma unroll
    for (int j = 0; j < 6; j++) {
        u64 r0 = woP[j * 4], r1 = woP[j * 4 + 1], r2 = woP[j * 4 + 2];
        u64 oa = rep2(o1[j]), ob = rep2(o2[j]);
        x1a[0] = fma2(oa, r0, x1a[0]); x1a[1] = fma2(oa, r1, x1a[1]); x1a[2] = fma2(oa, r2, x1a[2]);
        x1b[0] = fma2(ob, r0, x1b[0]); x1b[1] = fma2(ob, r1, x1b[1]); x1b[2] = fma2(ob, r2, x1b[2]);
    }
    float xa[6], xb[6];
#pragma unroll
    for (int p = 0; p < 3; p++) {
        float2 fa = upk2(x1a[p]); xa[2 * p] = fa.x; xa[2 * p + 1] = fa.y;
        float2 fb = upk2(x1b[p]); xb[2 * p] = fb.x; xb[2 * p + 1] = fb.y;
    }
    float ha[6], hb[6];
    ln6(xa, ha, sw + 256, sw + 264);
    ln6(xb, hb, sw + 256, sw + 264);

    u64 ffa[3] = {b1P[0], b1P[1], b1P[2]};
    u64 ffb[3] = {b1P[0], b1P[1], b1P[2]};
#pragma unroll
    for (int i = 0; i < 6; i++) {
        u64 r0 = w1P[i * 4], r1 = w1P[i * 4 + 1], r2 = w1P[i * 4 + 2];
        u64 va = rep2(ha[i]), vb = rep2(hb[i]);
        ffa[0] = fma2(va, r0, ffa[0]); ffa[1] = fma2(va, r1, ffa[1]); ffa[2] = fma2(va, r2, ffa[2]);
        ffb[0] = fma2(vb, r0, ffb[0]); ffb[1] = fma2(vb, r1, ffb[1]); ffb[2] = fma2(vb, r2, ffb[2]);
    }
    float ga[6], gb[6];
#pragma unroll
    for (int p = 0; p < 3; p++) {
        float2 fa = upk2(ffa[p]); ga[2 * p] = gelu_exact(fa.x); ga[2 * p + 1] = gelu_exact(fa.y);
        float2 fb = upk2(ffb[p]); gb[2 * p] = gelu_exact(fb.x); gb[2 * p + 1] = gelu_exact(fb.y);
    }
    u64 x2a[3], x2b[3];
#pragma unroll
    for (int p = 0; p < 3; p++) { x2a[p] = add2(x1a[p], b2P[p]); x2b[p] = add2(x1b[p], b2P[p]); }
#pragma unroll
    for (int j = 0; j < 6; j++) {
        u64 r0 = w2P[j * 4], r1 = w2P[j * 4 + 1], r2 = w2P[j * 4 + 2];
        u64 va = rep2(ga[j]), vb = rep2(gb[j]);
        x2a[0] = fma2(va, r0, x2a[0]); x2a[1] = fma2(va, r1, x2a[1]); x2a[2] = fma2(va, r2, x2a[2]);
        x2b[0] = fma2(vb, r0, x2b[0]); x2b[1] = fma2(vb, r1, x2b[1]); x2b[2] = fma2(vb, r2, x2b[2]);
    }
    float ta[6], tb[6], ya[6], yb[6];
#pragma unroll
    for (int p = 0; p < 3; p++) {
        float2 fa = upk2(x2a[p]); ta[2 * p] = fa.x; ta[2 * p + 1] = fa.y;
        float2 fb = upk2(x2b[p]); tb[2 * p] = fb.x; tb[2 * p + 1] = fb.y;
    }
    ln6(ta, ya, sw + 272, sw + 280);
    ln6(tb, yb, sw + 272, sw + 280);

    u64 la[7] = {0, 0, 0, 0, 0, 0, 0}, lb[7] = {0, 0, 0, 0, 0, 0, 0};
#pragma unroll
    for (int i = 0; i < 6; i++) {
        u64 va = rep2(ya[i]), vb = rep2(yb[i]);
#pragma unroll
        for (int p = 0; p < 7; p++) {
            u64 wr = whP[i * 8 + p];
            la[p] = fma2(va, wr, la[p]);
            lb[p] = fma2(vb, wr, lb[p]);
        }
    }
    int seq = base + lane;
    u64* oA = (u64*)(out + (seq * 34 + t1) * 14);
    u64* oB = (u64*)(out + (seq * 34 + t2) * 14);
#pragma unroll
    for (int p = 0; p < 7; p++) { oA[p] = la[p]; oB[p] = lb[p]; }
}

extern "C" void kernel_launch(void* const* d_in, const int* in_sizes, int n_in,
                              void* d_out, int out_size) {
    const int*   idx     = (const int*)d_in[0];
    const float* tok_emb = (const float*)d_in[1];
    const float* pos_enc = (const float*)d_in[2];
    const float* wq      = (const float*)d_in[3];
    const float* wk      = (const float*)d_in[4];
    const float* wv      = (const float*)d_in[5];
    const float* wo      = (const float*)d_in[6];
    const float* ln1_g   = (const float*)d_in[7];
    const float* ln1_b   = (const float*)d_in[8];
    const float* ln2_g   = (const float*)d_in[9];
    const float* ln2_b   = (const float*)d_in[10];
    const float* w1      = (const float*)d_in[11];
    const float* b1      = (const float*)d_in[12];
    const float* w2      = (const float*)d_in[13];
    const float* b2      = (const float*)d_in[14];
    const float* lnf_g   = (const float*)d_in[15];
    const float* lnf_b   = (const float*)d_in[16];
    const float* wh      = (const float*)d_in[17];

    int nseq = in_sizes[0] / T_SEQ;
    build_luts<<<1, 512>>>(tok_emb, pos_enc, wq, wk, wv, ln1_g, ln1_b);
    dim3 blk(32, 17);
    tf_main<<<nseq / 32, blk>>>(idx, (float*)d_out, wo, ln2_g, ln2_b,
                                w1, b1, w2, b2, lnf_g, lnf_b, wh);
}